// round 4
// baseline (speedup 1.0000x reference)
#include <cuda_runtime.h>

// ---------------------------------------------------------------------------
// cseft: algebraically restructured (no N x N score matrix).
//   K = y@W2, V = y@W3                                  [4096,1024]
//   B_s[h*128+d1, d2] = cw[h]*inv_sqrt/256 * sum_i K[s*256+i,h*128+d1]*V[s*256+i,h*128+d2]
//   C_s = W1 @ B_s                                      [512,128] x16
//   out[:, s*128:(s+1)*128] = x @ C_s                   [4096,2048]
// Total ~20.4 GFLOP vs ~82 GFLOP naive.
// ---------------------------------------------------------------------------

// Scratch (device globals; no allocation allowed)
__device__ float g_K[4096 * 1024];
__device__ float g_V[4096 * 1024];
__device__ float g_Bm[16 * 1024 * 128];
__device__ float g_Cm[16 * 512 * 128];

// Generic fp32 GEMM: C[M,N] = A[M,K] @ B[K,N], row-major, tiles 128x128x16,
// 256 threads, 8x8 micro-tile, double-buffered smem.
// M,N multiples of 128; K multiple of 16. Batched over blockIdx.z.
__global__ __launch_bounds__(256) void gemm_f32(
    const float* __restrict__ A, int lda, long long sA,
    const float* __restrict__ B, int ldb, long long sB,
    float* __restrict__ C, int ldc, long long sC,
    int K)
{
    constexpr int BM = 128, BN = 128, BK = 16, TM = 8, TN = 8;
    __shared__ float As[2][BK][BM];
    __shared__ float Bs[2][BK][BN];

    const int bz = blockIdx.z;
    A += (long long)bz * sA;
    B += (long long)bz * sB;
    C += (long long)bz * sC;

    const int rowBase = blockIdx.y * BM;
    const int colBase = blockIdx.x * BN;
    const int tid = threadIdx.x;
    const int tx = tid & 15;        // N dim
    const int ty = tid >> 4;        // M dim
    // A loader: 128x16 floats = 512 float4; 2 per thread
    const int aRow = tid >> 2;            // 0..63
    const int aCol = (tid & 3) * 4;       // 0,4,8,12
    // B loader: 16x128 floats = 512 float4; 2 per thread
    const int bRow = tid >> 5;            // 0..7
    const int bCol = (tid & 31) * 4;      // 0..124

    float acc[TM][TN] = {};

    // Prologue: load tile 0 into buffer 0.
    {
#pragma unroll
        for (int r = 0; r < 2; r++) {
            int m = aRow + r * 64;
            float4 v = *reinterpret_cast<const float4*>(
                A + (long long)(rowBase + m) * lda + aCol);
            As[0][aCol + 0][m] = v.x;
            As[0][aCol + 1][m] = v.y;
            As[0][aCol + 2][m] = v.z;
            As[0][aCol + 3][m] = v.w;
        }
#pragma unroll
        for (int r = 0; r < 2; r++) {
            int kk = bRow + r * 8;
            *reinterpret_cast<float4*>(&Bs[0][kk][bCol]) =
                *reinterpret_cast<const float4*>(
                    B + (long long)kk * ldb + colBase + bCol);
        }
    }
    __syncthreads();

    int buf = 0;
    for (int k0 = 0; k0 < K; k0 += BK) {
        const int knext = k0 + BK;
        float4 pa[2], pb[2];
        if (knext < K) {
            // Prefetch next tile into registers (loads issued before FMA loop).
#pragma unroll
            for (int r = 0; r < 2; r++) {
                int m = aRow + r * 64;
                pa[r] = *reinterpret_cast<const float4*>(
                    A + (long long)(rowBase + m) * lda + knext + aCol);
            }
#pragma unroll
            for (int r = 0; r < 2; r++) {
                int kk = bRow + r * 8;
                pb[r] = *reinterpret_cast<const float4*>(
                    B + (long long)(knext + kk) * ldb + colBase + bCol);
            }
        }

#pragma unroll
        for (int kk = 0; kk < BK; kk++) {
            float a[TM], b[TN];
            *reinterpret_cast<float4*>(a)     = *reinterpret_cast<const float4*>(&As[buf][kk][ty * TM]);
            *reinterpret_cast<float4*>(a + 4) = *reinterpret_cast<const float4*>(&As[buf][kk][ty * TM + 4]);
            *reinterpret_cast<float4*>(b)     = *reinterpret_cast<const float4*>(&Bs[buf][kk][tx * TN]);
            *reinterpret_cast<float4*>(b + 4) = *reinterpret_cast<const float4*>(&Bs[buf][kk][tx * TN + 4]);
#pragma unroll
            for (int i = 0; i < TM; i++)
#pragma unroll
                for (int j = 0; j < TN; j++)
                    acc[i][j] = fmaf(a[i], b[j], acc[i][j]);
        }

        if (knext >= K) break;

        const int nb = buf ^ 1;
#pragma unroll
        for (int r = 0; r < 2; r++) {
            int m = aRow + r * 64;
            As[nb][aCol + 0][m] = pa[r].x;
            As[nb][aCol + 1][m] = pa[r].y;
            As[nb][aCol + 2][m] = pa[r].z;
            As[nb][aCol + 3][m] = pa[r].w;
        }
#pragma unroll
        for (int r = 0; r < 2; r++) {
            int kk = bRow + r * 8;
            *reinterpret_cast<float4*>(&Bs[nb][kk][bCol]) = pb[r];
        }
        __syncthreads();
        buf = nb;
    }

#pragma unroll
    for (int i = 0; i < TM; i++) {
        long long m = rowBase + ty * TM + i;
#pragma unroll
        for (int j = 0; j < TN; j += 4) {
            float4 v = make_float4(acc[i][j], acc[i][j + 1], acc[i][j + 2], acc[i][j + 3]);
            *reinterpret_cast<float4*>(C + m * ldc + colBase + tx * TN + j) = v;
        }
    }
}

// B_s = scale * K_s^T @ V_s per (h = blockIdx.x, s = blockIdx.y).
// Reduction over i = 0..255; double-buffered smem.
__global__ __launch_bounds__(256) void ktv_f32(
    const float* __restrict__ Kp, const float* __restrict__ Vp,
    const float* __restrict__ conv_w, float* __restrict__ Bout)
{
    constexpr int BK = 16;
    __shared__ float As[2][BK][128];
    __shared__ float Bs[2][BK][128];

    const int h = blockIdx.x;
    const int s = blockIdx.y;
    const float* Ag = Kp + (long long)s * 256 * 1024 + h * 128;
    const float* Bg = Vp + (long long)s * 256 * 1024 + h * 128;
    float* Cg = Bout + (long long)s * 1024 * 128 + (long long)h * 128 * 128;

    const int tid = threadIdx.x;
    const int tx = tid & 15;
    const int ty = tid >> 4;
    const int lRow = tid >> 5;            // 0..7
    const int lCol = (tid & 31) * 4;      // 0..124

    float acc[8][8] = {};

    // Prologue: tile 0 -> buffer 0
#pragma unroll
    for (int r = 0; r < 2; r++) {
        int kk = lRow + r * 8;
        *reinterpret_cast<float4*>(&As[0][kk][lCol]) =
            *reinterpret_cast<const float4*>(Ag + (long long)kk * 1024 + lCol);
        *reinterpret_cast<float4*>(&Bs[0][kk][lCol]) =
            *reinterpret_cast<const float4*>(Bg + (long long)kk * 1024 + lCol);
    }
    __syncthreads();

    int buf = 0;
    for (int k0 = 0; k0 < 256; k0 += BK) {
        const int knext = k0 + BK;
        float4 pa[2], pb[2];
        if (knext < 256) {
#pragma unroll
            for (int r = 0; r < 2; r++) {
                int kk = lRow + r * 8;
                pa[r] = *reinterpret_cast<const float4*>(Ag + (long long)(knext + kk) * 1024 + lCol);
                pb[r] = *reinterpret_cast<const float4*>(Bg + (long long)(knext + kk) * 1024 + lCol);
            }
        }

#pragma unroll
        for (int kk = 0; kk < BK; kk++) {
            float a[8], b[8];
            *reinterpret_cast<float4*>(a)     = *reinterpret_cast<const float4*>(&As[buf][kk][ty * 8]);
            *reinterpret_cast<float4*>(a + 4) = *reinterpret_cast<const float4*>(&As[buf][kk][ty * 8 + 4]);
            *reinterpret_cast<float4*>(b)     = *reinterpret_cast<const float4*>(&Bs[buf][kk][tx * 8]);
            *reinterpret_cast<float4*>(b + 4) = *reinterpret_cast<const float4*>(&Bs[buf][kk][tx * 8 + 4]);
#pragma unroll
            for (int i = 0; i < 8; i++)
#pragma unroll
                for (int j = 0; j < 8; j++)
                    acc[i][j] = fmaf(a[i], b[j], acc[i][j]);
        }

        if (knext >= 256) break;

        const int nb = buf ^ 1;
#pragma unroll
        for (int r = 0; r < 2; r++) {
            int kk = lRow + r * 8;
            *reinterpret_cast<float4*>(&As[nb][kk][lCol]) = pa[r];
            *reinterpret_cast<float4*>(&Bs[nb][kk][lCol]) = pb[r];
        }
        __syncthreads();
        buf = nb;
    }

    // scale = conv_w[h] * (1/sqrt(Dh)) / nItem
    const float scale = conv_w[h] * (0.08838834764831845f / 256.0f);
#pragma unroll
    for (int i = 0; i < 8; i++) {
        int d1 = ty * 8 + i;
#pragma unroll
        for (int j = 0; j < 8; j += 4) {
            float4 v = make_float4(acc[i][j] * scale, acc[i][j + 1] * scale,
                                   acc[i][j + 2] * scale, acc[i][j + 3] * scale);
            *reinterpret_cast<float4*>(Cg + (long long)d1 * 128 + tx * 8 + j) = v;
        }
    }
}

extern "C" void kernel_launch(void* const* d_in, const int* in_sizes, int n_in,
                              void* d_out, int out_size)
{
    const float* x  = (const float*)d_in[0];   // [4096, 512]
    const float* y  = (const float*)d_in[1];   // [4096, 512]
    const float* W1 = (const float*)d_in[2];   // [512, 1024]
    const float* W2 = (const float*)d_in[3];   // [512, 1024]
    const float* W3 = (const float*)d_in[4];   // [512, 1024]
    const float* cw = (const float*)d_in[5];   // [8]
    float* out = (float*)d_out;                // [4096, 16, 128] = [4096, 2048]

    float *Kb, *Vb, *Bm, *Cm;
    cudaGetSymbolAddress((void**)&Kb, g_K);
    cudaGetSymbolAddress((void**)&Vb, g_V);
    cudaGetSymbolAddress((void**)&Bm, g_Bm);
    cudaGetSymbolAddress((void**)&Cm, g_Cm);

    dim3 t(256);

    // Stage A: K = y@W2, V = y@W3   (M=4096, N=1024, K=512)
    gemm_f32<<<dim3(8, 32, 1), t>>>(y, 512, 0, W2, 1024, 0, Kb, 1024, 0, 512);
    gemm_f32<<<dim3(8, 32, 1), t>>>(y, 512, 0, W3, 1024, 0, Vb, 1024, 0, 512);

    // Stage B: B_s = scale * K_s^T V_s  per (h, s)
    ktv_f32<<<dim3(8, 16), t>>>(Kb, Vb, cw, Bm);

    // Stage C: C_s = W1 @ B_s   (M=512, N=128, K=1024, batch 16)
    gemm_f32<<<dim3(1, 4, 16), t>>>(W1, 1024, 0,
                                    Bm, 128, 1024LL * 128,
                                    Cm, 128, 512LL * 128, 1024);

    // Stage D: out[:, s*128:(s+1)*128] = x @ C_s  (M=4096, N=128, K=512, batch 16)
    gemm_f32<<<dim3(1, 32, 16), t>>>(x, 512, 0,
                                     Cm, 128, 512LL * 128,
                                     out, 2048, 128, 512);
}

// round 7
// speedup vs baseline: 1.4764x; 1.4764x over previous
#include <cuda_runtime.h>
#include <cuda_bf16.h>
#include <cstdint>

#define DINL __device__ __forceinline__

// ---------------------------------------------------------------------------
// cseft via mma.sync bf16 hi/lo 3-pass split (base compute_103-safe).
//   Q  = x@W1                 [4096,1024]  bf16-split, row-major (K-major)
//   KT = (y@W2)^T             [1024,4096]  bf16-split
//   VT = (y@W3)^T             [1024,4096]  bf16-split
//   BmT[s][d2][hd1] = cw[h]*c * sum_i KT[hd1, s*256+i] VT[h*128+d2, s*256+i]
//   out[:, s*128:(s+1)*128] = Q @ BmT_s^T   (fp32)
// All GEMMs: D = A . B^T with A,B K-major.
// ---------------------------------------------------------------------------

// ---------- device scratch ----------
__device__ __nv_bfloat16 g_xhi[4096*512],  g_xlo[4096*512];
__device__ __nv_bfloat16 g_yhi[4096*512],  g_ylo[4096*512];
__device__ __nv_bfloat16 g_w1hi[1024*512], g_w1lo[1024*512];
__device__ __nv_bfloat16 g_w2hi[1024*512], g_w2lo[1024*512];
__device__ __nv_bfloat16 g_w3hi[1024*512], g_w3lo[1024*512];
__device__ __nv_bfloat16 g_qhi[4096*1024], g_qlo[4096*1024];
__device__ __nv_bfloat16 g_kthi[1024*4096], g_ktlo[1024*4096];
__device__ __nv_bfloat16 g_vthi[1024*4096], g_vtlo[1024*4096];
__device__ __nv_bfloat16 g_bmhi[16*128*1024], g_bmlo[16*128*1024];

// ---------- helpers ----------
DINL uint32_t smem_u32(const void* p) {
    uint32_t a;
    asm("{ .reg .u64 t; cvta.to.shared.u64 t, %1; cvt.u32.u64 %0, t; }"
        : "=r"(a) : "l"(p));
    return a;
}
DINL void cp16(uint32_t s, const void* g) {
    asm volatile("cp.async.cg.shared.global [%0], [%1], 16;" :: "r"(s), "l"(g));
}
DINL void cp_commit() { asm volatile("cp.async.commit_group;" ::: "memory"); }
DINL void cp_wait1()  { asm volatile("cp.async.wait_group 1;" ::: "memory"); }
DINL void cp_wait0()  { asm volatile("cp.async.wait_group 0;" ::: "memory"); }

DINL void mma16816(float& d0, float& d1, float& d2, float& d3,
                   uint32_t a0, uint32_t a1, uint32_t a2, uint32_t a3,
                   uint32_t b0, uint32_t b1) {
    asm volatile(
        "mma.sync.aligned.m16n8k16.row.col.f32.bf16.bf16.f32 "
        "{%0,%1,%2,%3}, {%4,%5,%6,%7}, {%8,%9}, {%0,%1,%2,%3};"
        : "+f"(d0), "+f"(d1), "+f"(d2), "+f"(d3)
        : "r"(a0), "r"(a1), "r"(a2), "r"(a3), "r"(b0), "r"(b1));
}

// ---------- conversion kernels ----------
__global__ void k_split(const float* __restrict__ in,
                        __nv_bfloat16* __restrict__ hi,
                        __nv_bfloat16* __restrict__ lo, int n) {
    for (int i = blockIdx.x * blockDim.x + threadIdx.x; i < n;
         i += gridDim.x * blockDim.x) {
        float v = in[i];
        __nv_bfloat16 h = __float2bfloat16(v);
        hi[i] = h;
        lo[i] = __float2bfloat16(v - __bfloat162float(h));
    }
}
// in [R,C] row-major -> out [C,R] transposed hi/lo
__global__ void k_splitT(const float* __restrict__ in,
                         __nv_bfloat16* __restrict__ hiT,
                         __nv_bfloat16* __restrict__ loT, int R, int C) {
    for (int i = blockIdx.x * blockDim.x + threadIdx.x; i < R * C;
         i += gridDim.x * blockDim.x) {
        int r = i / C, c = i % C;
        float v = in[i];
        __nv_bfloat16 h = __float2bfloat16(v);
        long long o = (long long)c * R + r;
        hiT[o] = h;
        loT[o] = __float2bfloat16(v - __bfloat162float(h));
    }
}

// ---------------------------------------------------------------------------
// HMMA GEMM: C[128,128] tile = sum_K (Ahi Bhi^T + Ahi Blo^T + Alo Bhi^T).
// A [Mtot,Ktot], B [Ntot,Ktot], bf16 K-major. BK = 64, double-buffered cp.async.
// 256 threads = 8 warps; warp (wm = w&1, wn = w>>1) owns rows wm*64..+63,
// cols wn*32..+31 of the tile; m16n8k16 fragments, 16 HMMA per k-step.
// MODE 0: fp32 C.  MODE 1: bf16-split C.  MODE 2: bf16-split C^T.
// Batch over blockIdx.z: z1=z/zdiv, z2=z%zdiv; scale = sfac*(swp?swp[z1]:1).
// ---------------------------------------------------------------------------
#define SA_W 36            // smem row stride in b32 words (72 bf16)
#define TILE_B 18432       // 128 * 144 bytes

template <int MODE>
__global__ __launch_bounds__(256) void tc_gemm(
    const __nv_bfloat16* __restrict__ Ahi, const __nv_bfloat16* __restrict__ Alo, int lda,
    const __nv_bfloat16* __restrict__ Bhi, const __nv_bfloat16* __restrict__ Blo, int ldb,
    int Ktot,
    float* __restrict__ Cf, __nv_bfloat16* __restrict__ Chi,
    __nv_bfloat16* __restrict__ Clo, int ldc,
    int zdiv,
    long long aOff1, long long aOff2, long long bOff1, long long bOff2,
    long long cOff1, long long cOff2,
    const float* __restrict__ swp, float sfac)
{
    extern __shared__ char sm[];
    const uint32_t smb = smem_u32(sm);

    const int tid = threadIdx.x;
    const int wid = tid >> 5;
    const int lane = tid & 31;
    const int g = lane >> 2;       // 0..7
    const int tig = lane & 3;      // 0..3
    const int wm = wid & 1;        // m half
    const int wn = wid >> 1;       // n quarter

    const int z = blockIdx.z;
    const int z1 = z / zdiv, z2 = z % zdiv;
    const long long offA = (long long)z1 * aOff1 + (long long)z2 * aOff2;
    const long long offB = (long long)z1 * bOff1 + (long long)z2 * bOff2;
    const long long offC = (long long)z1 * cOff1 + (long long)z2 * cOff2;
    const float scale = sfac * (swp ? swp[z1] : 1.0f);

    const int rowBase = blockIdx.y * 128;
    const int colBase = blockIdx.x * 128;

    const __nv_bfloat16* pA[2] = { Ahi + offA + (long long)rowBase * lda,
                                   Alo + offA + (long long)rowBase * lda };
    const __nv_bfloat16* pB[2] = { Bhi + offB + (long long)colBase * ldb,
                                   Blo + offB + (long long)colBase * ldb };

    // loader coords: 1024 uint4 per tile; this thread does idx = tid + 256*i
    // r = idx>>3 (row 0..127), j = idx&7 (16B chunk)
    auto load_chunk = [&](int buf, int k0) {
        const uint32_t base = smb + (uint32_t)buf * (4 * TILE_B);
#pragma unroll
        for (int i = 0; i < 4; ++i) {
            const int idx = tid + (i << 8);
            const int r = idx >> 3, j = idx & 7;
            const uint32_t so = (uint32_t)(r * 144 + j * 16);
            const long long ga = (long long)r * lda + k0 + j * 8;
            const long long gb = (long long)r * ldb + k0 + j * 8;
            cp16(base + so,              pA[0] + ga);
            cp16(base + TILE_B + so,     pA[1] + ga);
            cp16(base + 2 * TILE_B + so, pB[0] + gb);
            cp16(base + 3 * TILE_B + so, pB[1] + gb);
        }
        cp_commit();
    };

    float acc[4][4][4];
#pragma unroll
    for (int i = 0; i < 4; ++i)
#pragma unroll
        for (int j = 0; j < 4; ++j)
#pragma unroll
            for (int q = 0; q < 4; ++q) acc[i][j][q] = 0.0f;

    const int nchunks = Ktot >> 6;
    load_chunk(0, 0);

    for (int c = 0; c < nchunks; ++c) {
        if (c + 1 < nchunks) {
            load_chunk((c + 1) & 1, (c + 1) << 6);
            cp_wait1();
        } else {
            cp_wait0();
        }
        __syncthreads();

        const uint32_t bufb = smb + (uint32_t)(c & 1) * (4 * TILE_B);

#pragma unroll
        for (int pass = 0; pass < 3; ++pass) {
            const uint32_t sA = bufb + (pass == 2 ? TILE_B : 0);
            const uint32_t sB = bufb + 2 * TILE_B + (pass == 1 ? TILE_B : 0);

#pragma unroll
            for (int ks = 0; ks < 4; ++ks) {
                uint32_t a[4][4], b[4][2];
#pragma unroll
                for (int mi = 0; mi < 4; ++mi) {
                    const int r0 = wm * 64 + mi * 16 + g;
                    const uint32_t w0 = sA + (uint32_t)(r0 * 144) + (uint32_t)((ks * 8 + tig) * 4);
                    const uint32_t w1 = w0 + 8 * 144;
                    asm volatile("ld.shared.b32 %0, [%1];" : "=r"(a[mi][0]) : "r"(w0));
                    asm volatile("ld.shared.b32 %0, [%1];" : "=r"(a[mi][1]) : "r"(w1));
                    asm volatile("ld.shared.b32 %0, [%1];" : "=r"(a[mi][2]) : "r"(w0 + 16));
                    asm volatile("ld.shared.b32 %0, [%1];" : "=r"(a[mi][3]) : "r"(w1 + 16));
                }
#pragma unroll
                for (int ni = 0; ni < 4; ++ni) {
                    const int rn = wn * 32 + ni * 8 + g;
                    const uint32_t w0 = sB + (uint32_t)(rn * 144) + (uint32_t)((ks * 8 + tig) * 4);
                    asm volatile("ld.shared.b32 %0, [%1];" : "=r"(b[ni][0]) : "r"(w0));
                    asm volatile("ld.shared.b32 %0, [%1];" : "=r"(b[ni][1]) : "r"(w0 + 16));
                }
#pragma unroll
                for (int mi = 0; mi < 4; ++mi)
#pragma unroll
                    for (int ni = 0; ni < 4; ++ni)
                        mma16816(acc[mi][ni][0], acc[mi][ni][1],
                                 acc[mi][ni][2], acc[mi][ni][3],
                                 a[mi][0], a[mi][1], a[mi][2], a[mi][3],
                                 b[ni][0], b[ni][1]);
            }
        }
        __syncthreads();
    }

    // ---- epilogue ----
#pragma unroll
    for (int mi = 0; mi < 4; ++mi) {
        const long long r0 = rowBase + wm * 64 + mi * 16 + g;
        const long long r1 = r0 + 8;
#pragma unroll
        for (int ni = 0; ni < 4; ++ni) {
            const long long col = colBase + wn * 32 + ni * 8 + tig * 2;
            const float v00 = acc[mi][ni][0] * scale;
            const float v01 = acc[mi][ni][1] * scale;
            const float v10 = acc[mi][ni][2] * scale;
            const float v11 = acc[mi][ni][3] * scale;

            if (MODE == 0) {
                *(float2*)(Cf + offC + r0 * ldc + col) = make_float2(v00, v01);
                *(float2*)(Cf + offC + r1 * ldc + col) = make_float2(v10, v11);
            } else if (MODE == 1) {
                __nv_bfloat16 h00 = __float2bfloat16(v00);
                __nv_bfloat16 h01 = __float2bfloat16(v01);
                __nv_bfloat16 h10 = __float2bfloat16(v10);
                __nv_bfloat16 h11 = __float2bfloat16(v11);
                Chi[offC + r0 * ldc + col]     = h00;
                Chi[offC + r0 * ldc + col + 1] = h01;
                Chi[offC + r1 * ldc + col]     = h10;
                Chi[offC + r1 * ldc + col + 1] = h11;
                Clo[offC + r0 * ldc + col]     = __float2bfloat16(v00 - __bfloat162float(h00));
                Clo[offC + r0 * ldc + col + 1] = __float2bfloat16(v01 - __bfloat162float(h01));
                Clo[offC + r1 * ldc + col]     = __float2bfloat16(v10 - __bfloat162float(h10));
                Clo[offC + r1 * ldc + col + 1] = __float2bfloat16(v11 - __bfloat162float(h11));
            } else {
                __nv_bfloat16 h00 = __float2bfloat16(v00);
                __nv_bfloat16 h01 = __float2bfloat16(v01);
                __nv_bfloat16 h10 = __float2bfloat16(v10);
                __nv_bfloat16 h11 = __float2bfloat16(v11);
                Chi[offC + col * ldc + r0]       = h00;
                Chi[offC + (col + 1) * ldc + r0] = h01;
                Chi[offC + col * ldc + r1]       = h10;
                Chi[offC + (col + 1) * ldc + r1] = h11;
                Clo[offC + col * ldc + r0]       = __float2bfloat16(v00 - __bfloat162float(h00));
                Clo[offC + (col + 1) * ldc + r0] = __float2bfloat16(v01 - __bfloat162float(h01));
                Clo[offC + col * ldc + r1]       = __float2bfloat16(v10 - __bfloat162float(h10));
                Clo[offC + (col + 1) * ldc + r1] = __float2bfloat16(v11 - __bfloat162float(h11));
            }
        }
    }
}

// ---------------------------------------------------------------------------
extern "C" void kernel_launch(void* const* d_in, const int* in_sizes, int n_in,
                              void* d_out, int out_size)
{
    const float* x  = (const float*)d_in[0];   // [4096, 512]
    const float* y  = (const float*)d_in[1];   // [4096, 512]
    const float* W1 = (const float*)d_in[2];   // [512, 1024]
    const float* W2 = (const float*)d_in[3];   // [512, 1024]
    const float* W3 = (const float*)d_in[4];   // [512, 1024]
    const float* cw = (const float*)d_in[5];   // [8]
    float* out = (float*)d_out;                // [4096, 2048]

    __nv_bfloat16 *xhi, *xlo, *yhi, *ylo;
    __nv_bfloat16 *w1hi, *w1lo, *w2hi, *w2lo, *w3hi, *w3lo;
    __nv_bfloat16 *qhi, *qlo, *kthi, *ktlo, *vthi, *vtlo, *bmhi, *bmlo;
    cudaGetSymbolAddress((void**)&xhi, g_xhi);   cudaGetSymbolAddress((void**)&xlo, g_xlo);
    cudaGetSymbolAddress((void**)&yhi, g_yhi);   cudaGetSymbolAddress((void**)&ylo, g_ylo);
    cudaGetSymbolAddress((void**)&w1hi, g_w1hi); cudaGetSymbolAddress((void**)&w1lo, g_w1lo);
    cudaGetSymbolAddress((void**)&w2hi, g_w2hi); cudaGetSymbolAddress((void**)&w2lo, g_w2lo);
    cudaGetSymbolAddress((void**)&w3hi, g_w3hi); cudaGetSymbolAddress((void**)&w3lo, g_w3lo);
    cudaGetSymbolAddress((void**)&qhi, g_qhi);   cudaGetSymbolAddress((void**)&qlo, g_qlo);
    cudaGetSymbolAddress((void**)&kthi, g_kthi); cudaGetSymbolAddress((void**)&ktlo, g_ktlo);
    cudaGetSymbolAddress((void**)&vthi, g_vthi); cudaGetSymbolAddress((void**)&vtlo, g_vtlo);
    cudaGetSymbolAddress((void**)&bmhi, g_bmhi); cudaGetSymbolAddress((void**)&bmlo, g_bmlo);

    const int SMEM_BYTES = 2 * 4 * TILE_B;   // 147456
    cudaFuncSetAttribute(tc_gemm<0>, cudaFuncAttributeMaxDynamicSharedMemorySize, SMEM_BYTES);
    cudaFuncSetAttribute(tc_gemm<1>, cudaFuncAttributeMaxDynamicSharedMemorySize, SMEM_BYTES);
    cudaFuncSetAttribute(tc_gemm<2>, cudaFuncAttributeMaxDynamicSharedMemorySize, SMEM_BYTES);

    // --- conversions ---
    k_split<<<2048, 256>>>(x, xhi, xlo, 4096 * 512);
    k_split<<<2048, 256>>>(y, yhi, ylo, 4096 * 512);
    k_splitT<<<2048, 256>>>(W1, w1hi, w1lo, 512, 1024);
    k_splitT<<<2048, 256>>>(W2, w2hi, w2lo, 512, 1024);
    k_splitT<<<2048, 256>>>(W3, w3hi, w3lo, 512, 1024);

    dim3 t(256);

    // G1: Q = x@W1 -> bf16 split [4096,1024]
    tc_gemm<1><<<dim3(8, 32, 1), t, SMEM_BYTES>>>(
        xhi, xlo, 512, w1hi, w1lo, 512, 512,
        nullptr, qhi, qlo, 1024,
        1, 0, 0, 0, 0, 0, 0, nullptr, 1.0f);

    // G2: KT = (y@W2)^T -> bf16 split [1024,4096]
    tc_gemm<2><<<dim3(8, 32, 1), t, SMEM_BYTES>>>(
        yhi, ylo, 512, w2hi, w2lo, 512, 512,
        nullptr, kthi, ktlo, 4096,
        1, 0, 0, 0, 0, 0, 0, nullptr, 1.0f);

    // G3: VT = (y@W3)^T -> bf16 split [1024,4096]
    tc_gemm<2><<<dim3(8, 32, 1), t, SMEM_BYTES>>>(
        yhi, ylo, 512, w3hi, w3lo, 512, 512,
        nullptr, vthi, vtlo, 4096,
        1, 0, 0, 0, 0, 0, 0, nullptr, 1.0f);

    // G4: per z = h*16+s: D[d1,d2] = KT[h*128+d1, s*256+:256] . VT[h*128+d2, ...]^T
    //     scaled by cw[h]*inv_sqrt/256, stored transposed into BmT[s][d2][h*128+d1]
    tc_gemm<2><<<dim3(1, 1, 128), t, SMEM_BYTES>>>(
        kthi, ktlo, 4096, vthi, vtlo, 4096, 256,
        nullptr, bmhi, bmlo, 1024,
        16,
        128LL * 4096, 256LL,        // A: +h*128 rows, +s*256 k-offset
        128LL * 4096, 256LL,        // B: same
        128LL, 128LL * 1024,        // C: +h*128 col-offset, +s slab
        cw, 0.08838834764831845f / 256.0f);

    // G5: out[:, s*128:(s+1)*128] = Q @ BmT_s^T  (fp32)
    tc_gemm<0><<<dim3(1, 32, 16), t, SMEM_BYTES>>>(
        qhi, qlo, 1024, bmhi, bmlo, 1024, 1024,
        out, nullptr, nullptr, 2048,
        16,
        0, 0,                        // A: Q shared
        0, 128LL * 1024,             // B: +s slab
        0, 128LL,                    // C: +s*128 col offset
        nullptr, 1.0f);
}

// round 12
// speedup vs baseline: 2.1373x; 1.4477x over previous
#include <cuda_runtime.h>
#include <cuda_bf16.h>
#include <cstdint>

#define DINL __device__ __forceinline__

// ---------------------------------------------------------------------------
// cseft via mma.sync bf16 hi/lo 3-pass split (base compute_103-safe).
// Cheaper factoring (no Q):
//   KT = (y@W2)^T             [1024,4096]  bf16-split
//   VT = (y@W3)^T             [1024,4096]  bf16-split
//   BmT[s][d2][hd1] = cw[h]*c * sum_i KT[hd1, s*256+i] VT[h*128+d2, s*256+i]
//   CT[s][d2][din]  = (W1 @ Bm_s)^T       [16][128][512] bf16-split
//   out[:, s*128:(s+1)*128] = x @ CT_s^T   (fp32)
// All GEMMs: D = A . B^T with A,B K-major.  10.2 GMAC (x3 passes).
// ---------------------------------------------------------------------------

// ---------- device scratch ----------
__device__ __nv_bfloat16 g_xhi[4096*512],   g_xlo[4096*512];
__device__ __nv_bfloat16 g_yhi[4096*512],   g_ylo[4096*512];
__device__ __nv_bfloat16 g_w1hi[512*1024],  g_w1lo[512*1024];    // non-transposed
__device__ __nv_bfloat16 g_w2thi[1024*512], g_w2tlo[1024*512];   // transposed
__device__ __nv_bfloat16 g_w3thi[1024*512], g_w3tlo[1024*512];
__device__ __nv_bfloat16 g_kthi[1024*4096], g_ktlo[1024*4096];
__device__ __nv_bfloat16 g_vthi[1024*4096], g_vtlo[1024*4096];
__device__ __nv_bfloat16 g_bmhi[16*128*1024], g_bmlo[16*128*1024];
__device__ __nv_bfloat16 g_cthi[16*128*512],  g_ctlo[16*128*512];

// ---------- helpers ----------
DINL uint32_t smem_u32(const void* p) {
    uint32_t a;
    asm("{ .reg .u64 t; cvta.to.shared.u64 t, %1; cvt.u32.u64 %0, t; }"
        : "=r"(a) : "l"(p));
    return a;
}
DINL void cp16(uint32_t s, const void* g) {
    asm volatile("cp.async.cg.shared.global [%0], [%1], 16;" :: "r"(s), "l"(g));
}
DINL void cp_commit() { asm volatile("cp.async.commit_group;" ::: "memory"); }
DINL void cp_wait1()  { asm volatile("cp.async.wait_group 1;" ::: "memory"); }
DINL void cp_wait0()  { asm volatile("cp.async.wait_group 0;" ::: "memory"); }

DINL void mma16816(float& d0, float& d1, float& d2, float& d3,
                   uint32_t a0, uint32_t a1, uint32_t a2, uint32_t a3,
                   uint32_t b0, uint32_t b1) {
    asm volatile(
        "mma.sync.aligned.m16n8k16.row.col.f32.bf16.bf16.f32 "
        "{%0,%1,%2,%3}, {%4,%5,%6,%7}, {%8,%9}, {%0,%1,%2,%3};"
        : "+f"(d0), "+f"(d1), "+f"(d2), "+f"(d3)
        : "r"(a0), "r"(a1), "r"(a2), "r"(a3), "r"(b0), "r"(b1));
}

// ---------- conversion kernels ----------
// Elementwise split, vectorized: float4 in, 2x bf16x2 out. n % 4 == 0.
__global__ void k_split4(const float4* __restrict__ in,
                         uint2* __restrict__ hi, uint2* __restrict__ lo, int n4) {
    for (int i = blockIdx.x * blockDim.x + threadIdx.x; i < n4;
         i += gridDim.x * blockDim.x) {
        float4 v = in[i];
        __nv_bfloat16 h0 = __float2bfloat16(v.x), h1 = __float2bfloat16(v.y);
        __nv_bfloat16 h2 = __float2bfloat16(v.z), h3 = __float2bfloat16(v.w);
        __nv_bfloat162 H0 = __nv_bfloat162(h0, h1), H1 = __nv_bfloat162(h2, h3);
        __nv_bfloat162 L0 = __nv_bfloat162(__float2bfloat16(v.x - __bfloat162float(h0)),
                                           __float2bfloat16(v.y - __bfloat162float(h1)));
        __nv_bfloat162 L1 = __nv_bfloat162(__float2bfloat16(v.z - __bfloat162float(h2)),
                                           __float2bfloat16(v.w - __bfloat162float(h3)));
        hi[i] = make_uint2(*(uint32_t*)&H0, *(uint32_t*)&H1);
        lo[i] = make_uint2(*(uint32_t*)&L0, *(uint32_t*)&L1);
    }
}
// Tiled transpose-split: in [R,C] row-major -> out [C,R]. 32x32 tiles,
// blockDim (32,8). R,C multiples of 32.
__global__ void k_splitT(const float* __restrict__ in,
                         __nv_bfloat16* __restrict__ hiT,
                         __nv_bfloat16* __restrict__ loT, int R, int C) {
    __shared__ float t[32][33];
    const int bx = blockIdx.x * 32;   // col base (input)
    const int by = blockIdx.y * 32;   // row base (input)
    const int tx = threadIdx.x, ty = threadIdx.y;
#pragma unroll
    for (int i = 0; i < 32; i += 8)
        t[ty + i][tx] = in[(long long)(by + ty + i) * C + bx + tx];
    __syncthreads();
#pragma unroll
    for (int i = 0; i < 32; i += 8) {
        const float v = t[tx][ty + i];
        const __nv_bfloat16 h = __float2bfloat16(v);
        const long long o = (long long)(bx + ty + i) * R + by + tx;
        hiT[o] = h;
        loT[o] = __float2bfloat16(v - __bfloat162float(h));
    }
}

// ---------------------------------------------------------------------------
// HMMA GEMM: C[128,128] tile = sum_K (Ahi Bhi^T + Ahi Blo^T + Alo Bhi^T).
// A [Mtot,Ktot], B [Ntot,Ktot], bf16 K-major. BK = 64, double-buffered cp.async.
// 256 threads = 8 warps; warp (wm = w&1, wn = w>>1) owns rows wm*64..+63,
// cols wn*32..+31; m16n8k16 fragments, 16 HMMA per k-step per pass.
// MODE 0: fp32 C.  MODE 1: bf16-split C.  MODE 2: bf16-split C^T.
// Batch over blockIdx.z: z1=z/zdiv, z2=z%zdiv; scale = sfac*(swp?swp[z1]:1).
// ---------------------------------------------------------------------------
#define TILE_B 18432       // 128 * 144 bytes

template <int MODE>
__global__ __launch_bounds__(256) void tc_gemm(
    const __nv_bfloat16* __restrict__ Ahi, const __nv_bfloat16* __restrict__ Alo, int lda,
    const __nv_bfloat16* __restrict__ Bhi, const __nv_bfloat16* __restrict__ Blo, int ldb,
    int Ktot,
    float* __restrict__ Cf, __nv_bfloat16* __restrict__ Chi,
    __nv_bfloat16* __restrict__ Clo, int ldc,
    int zdiv,
    long long aOff1, long long aOff2, long long bOff1, long long bOff2,
    long long cOff1, long long cOff2,
    const float* __restrict__ swp, float sfac)
{
    extern __shared__ char sm[];
    const uint32_t smb = smem_u32(sm);

    const int tid = threadIdx.x;
    const int wid = tid >> 5;
    const int lane = tid & 31;
    const int g = lane >> 2;       // 0..7
    const int tig = lane & 3;      // 0..3
    const int wm = wid & 1;        // m half
    const int wn = wid >> 1;       // n quarter

    const int z = blockIdx.z;
    const int z1 = z / zdiv, z2 = z % zdiv;
    const long long offA = (long long)z1 * aOff1 + (long long)z2 * aOff2;
    const long long offB = (long long)z1 * bOff1 + (long long)z2 * bOff2;
    const long long offC = (long long)z1 * cOff1 + (long long)z2 * cOff2;
    const float scale = sfac * (swp ? swp[z1] : 1.0f);

    const int rowBase = blockIdx.y * 128;
    const int colBase = blockIdx.x * 128;

    const __nv_bfloat16* pA[2] = { Ahi + offA + (long long)rowBase * lda,
                                   Alo + offA + (long long)rowBase * lda };
    const __nv_bfloat16* pB[2] = { Bhi + offB + (long long)colBase * ldb,
                                   Blo + offB + (long long)colBase * ldb };

    auto load_chunk = [&](int buf, int k0) {
        const uint32_t base = smb + (uint32_t)buf * (4 * TILE_B);
#pragma unroll
        for (int i = 0; i < 4; ++i) {
            const int idx = tid + (i << 8);
            const int r = idx >> 3, j = idx & 7;
            const uint32_t so = (uint32_t)(r * 144 + j * 16);
            const long long ga = (long long)r * lda + k0 + j * 8;
            const long long gb = (long long)r * ldb + k0 + j * 8;
            cp16(base + so,              pA[0] + ga);
            cp16(base + TILE_B + so,     pA[1] + ga);
            cp16(base + 2 * TILE_B + so, pB[0] + gb);
            cp16(base + 3 * TILE_B + so, pB[1] + gb);
        }
        cp_commit();
    };

    float acc[4][4][4];
#pragma unroll
    for (int i = 0; i < 4; ++i)
#pragma unroll
        for (int j = 0; j < 4; ++j)
#pragma unroll
            for (int q = 0; q < 4; ++q) acc[i][j][q] = 0.0f;

    const int nchunks = Ktot >> 6;
    load_chunk(0, 0);

    for (int c = 0; c < nchunks; ++c) {
        if (c + 1 < nchunks) {
            load_chunk((c + 1) & 1, (c + 1) << 6);
            cp_wait1();
        } else {
            cp_wait0();
        }
        __syncthreads();

        const uint32_t bufb = smb + (uint32_t)(c & 1) * (4 * TILE_B);

#pragma unroll
        for (int pass = 0; pass < 3; ++pass) {
            const uint32_t sA = bufb + (pass == 2 ? TILE_B : 0);
            const uint32_t sB = bufb + 2 * TILE_B + (pass == 1 ? TILE_B : 0);

#pragma unroll
            for (int ks = 0; ks < 4; ++ks) {
                uint32_t a[4][4], b[4][2];
#pragma unroll
                for (int mi = 0; mi < 4; ++mi) {
                    const int r0 = wm * 64 + mi * 16 + g;
                    const uint32_t w0 = sA + (uint32_t)(r0 * 144) + (uint32_t)((ks * 8 + tig) * 4);
                    const uint32_t w1 = w0 + 8 * 144;
                    asm volatile("ld.shared.b32 %0, [%1];" : "=r"(a[mi][0]) : "r"(w0));
                    asm volatile("ld.shared.b32 %0, [%1];" : "=r"(a[mi][1]) : "r"(w1));
                    asm volatile("ld.shared.b32 %0, [%1];" : "=r"(a[mi][2]) : "r"(w0 + 16));
                    asm volatile("ld.shared.b32 %0, [%1];" : "=r"(a[mi][3]) : "r"(w1 + 16));
                }
#pragma unroll
                for (int ni = 0; ni < 4; ++ni) {
                    const int rn = wn * 32 + ni * 8 + g;
                    const uint32_t w0 = sB + (uint32_t)(rn * 144) + (uint32_t)((ks * 8 + tig) * 4);
                    asm volatile("ld.shared.b32 %0, [%1];" : "=r"(b[ni][0]) : "r"(w0));
                    asm volatile("ld.shared.b32 %0, [%1];" : "=r"(b[ni][1]) : "r"(w0 + 16));
                }
#pragma unroll
                for (int mi = 0; mi < 4; ++mi)
#pragma unroll
                    for (int ni = 0; ni < 4; ++ni)
                        mma16816(acc[mi][ni][0], acc[mi][ni][1],
                                 acc[mi][ni][2], acc[mi][ni][3],
                                 a[mi][0], a[mi][1], a[mi][2], a[mi][3],
                                 b[ni][0], b[ni][1]);
            }
        }
        __syncthreads();
    }

    // ---- epilogue ----
#pragma unroll
    for (int mi = 0; mi < 4; ++mi) {
        const long long r0 = rowBase + wm * 64 + mi * 16 + g;
        const long long r1 = r0 + 8;
#pragma unroll
        for (int ni = 0; ni < 4; ++ni) {
            const long long col = colBase + wn * 32 + ni * 8 + tig * 2;
            const float v00 = acc[mi][ni][0] * scale;
            const float v01 = acc[mi][ni][1] * scale;
            const float v10 = acc[mi][ni][2] * scale;
            const float v11 = acc[mi][ni][3] * scale;

            if (MODE == 0) {
                *(float2*)(Cf + offC + r0 * ldc + col) = make_float2(v00, v01);
                *(float2*)(Cf + offC + r1 * ldc + col) = make_float2(v10, v11);
            } else if (MODE == 1) {
                __nv_bfloat16 h00 = __float2bfloat16(v00);
                __nv_bfloat16 h01 = __float2bfloat16(v01);
                __nv_bfloat16 h10 = __float2bfloat16(v10);
                __nv_bfloat16 h11 = __float2bfloat16(v11);
                *(__nv_bfloat162*)(Chi + offC + r0 * ldc + col) = __nv_bfloat162(h00, h01);
                *(__nv_bfloat162*)(Chi + offC + r1 * ldc + col) = __nv_bfloat162(h10, h11);
                *(__nv_bfloat162*)(Clo + offC + r0 * ldc + col) =
                    __nv_bfloat162(__float2bfloat16(v00 - __bfloat162float(h00)),
                                   __float2bfloat16(v01 - __bfloat162float(h01)));
                *(__nv_bfloat162*)(Clo + offC + r1 * ldc + col) =
                    __nv_bfloat162(__float2bfloat16(v10 - __bfloat162float(h10)),
                                   __float2bfloat16(v11 - __bfloat162float(h11)));
            } else {
                __nv_bfloat16 h00 = __float2bfloat16(v00);
                __nv_bfloat16 h01 = __float2bfloat16(v01);
                __nv_bfloat16 h10 = __float2bfloat16(v10);
                __nv_bfloat16 h11 = __float2bfloat16(v11);
                Chi[offC + col * ldc + r0]       = h00;
                Chi[offC + (col + 1) * ldc + r0] = h01;
                Chi[offC + col * ldc + r1]       = h10;
                Chi[offC + (col + 1) * ldc + r1] = h11;
                Clo[offC + col * ldc + r0]       = __float2bfloat16(v00 - __bfloat162float(h00));
                Clo[offC + (col + 1) * ldc + r0] = __float2bfloat16(v01 - __bfloat162float(h01));
                Clo[offC + col * ldc + r1]       = __float2bfloat16(v10 - __bfloat162float(h10));
                Clo[offC + (col + 1) * ldc + r1] = __float2bfloat16(v11 - __bfloat162float(h11));
            }
        }
    }
}

// ---------------------------------------------------------------------------
extern "C" void kernel_launch(void* const* d_in, const int* in_sizes, int n_in,
                              void* d_out, int out_size)
{
    const float* x  = (const float*)d_in[0];   // [4096, 512]
    const float* y  = (const float*)d_in[1];   // [4096, 512]
    const float* W1 = (const float*)d_in[2];   // [512, 1024]
    const float* W2 = (const float*)d_in[3];   // [512, 1024]
    const float* W3 = (const float*)d_in[4];   // [512, 1024]
    const float* cw = (const float*)d_in[5];   // [8]
    float* out = (float*)d_out;                // [4096, 2048]

    __nv_bfloat16 *xhi, *xlo, *yhi, *ylo;
    __nv_bfloat16 *w1hi, *w1lo, *w2thi, *w2tlo, *w3thi, *w3tlo;
    __nv_bfloat16 *kthi, *ktlo, *vthi, *vtlo, *bmhi, *bmlo, *cthi, *ctlo;
    cudaGetSymbolAddress((void**)&xhi, g_xhi);     cudaGetSymbolAddress((void**)&xlo, g_xlo);
    cudaGetSymbolAddress((void**)&yhi, g_yhi);     cudaGetSymbolAddress((void**)&ylo, g_ylo);
    cudaGetSymbolAddress((void**)&w1hi, g_w1hi);   cudaGetSymbolAddress((void**)&w1lo, g_w1lo);
    cudaGetSymbolAddress((void**)&w2thi, g_w2thi); cudaGetSymbolAddress((void**)&w2tlo, g_w2tlo);
    cudaGetSymbolAddress((void**)&w3thi, g_w3thi); cudaGetSymbolAddress((void**)&w3tlo, g_w3tlo);
    cudaGetSymbolAddress((void**)&kthi, g_kthi);   cudaGetSymbolAddress((void**)&ktlo, g_ktlo);
    cudaGetSymbolAddress((void**)&vthi, g_vthi);   cudaGetSymbolAddress((void**)&vtlo, g_vtlo);
    cudaGetSymbolAddress((void**)&bmhi, g_bmhi);   cudaGetSymbolAddress((void**)&bmlo, g_bmlo);
    cudaGetSymbolAddress((void**)&cthi, g_cthi);   cudaGetSymbolAddress((void**)&ctlo, g_ctlo);

    const int SMEM_BYTES = 2 * 4 * TILE_B;   // 147456
    cudaFuncSetAttribute(tc_gemm<0>, cudaFuncAttributeMaxDynamicSharedMemorySize, SMEM_BYTES);
    cudaFuncSetAttribute(tc_gemm<1>, cudaFuncAttributeMaxDynamicSharedMemorySize, SMEM_BYTES);
    cudaFuncSetAttribute(tc_gemm<2>, cudaFuncAttributeMaxDynamicSharedMemorySize, SMEM_BYTES);

    dim3 t(256);

    // --- conversions ---
    k_split4<<<1024, 256>>>((const float4*)x, (uint2*)xhi, (uint2*)xlo, 4096 * 512 / 4);
    k_split4<<<1024, 256>>>((const float4*)y, (uint2*)yhi, (uint2*)ylo, 4096 * 512 / 4);
    k_split4<<<512, 256>>>((const float4*)W1, (uint2*)w1hi, (uint2*)w1lo, 512 * 1024 / 4);
    k_splitT<<<dim3(32, 16), dim3(32, 8)>>>(W2, w2thi, w2tlo, 512, 1024);
    k_splitT<<<dim3(32, 16), dim3(32, 8)>>>(W3, w3thi, w3tlo, 512, 1024);

    // G2: KT = (y@W2)^T -> bf16 split [1024,4096]
    tc_gemm<2><<<dim3(8, 32, 1), t, SMEM_BYTES>>>(
        yhi, ylo, 512, w2thi, w2tlo, 512, 512,
        nullptr, kthi, ktlo, 4096,
        1, 0, 0, 0, 0, 0, 0, nullptr, 1.0f);

    // G3: VT = (y@W3)^T -> bf16 split [1024,4096]
    tc_gemm<2><<<dim3(8, 32, 1), t, SMEM_BYTES>>>(
        yhi, ylo, 512, w3thi, w3tlo, 512, 512,
        nullptr, vthi, vtlo, 4096,
        1, 0, 0, 0, 0, 0, 0, nullptr, 1.0f);

    // G4: per z = h*16+s: D[d1,d2] = KT[h*128+d1, s*256+:256] . VT[h*128+d2, ...]^T
    //     scaled by cw[h]*inv_sqrt/256, stored transposed: BmT[s][d2][h*128+d1]
    tc_gemm<2><<<dim3(1, 1, 128), t, SMEM_BYTES>>>(
        kthi, ktlo, 4096, vthi, vtlo, 4096, 256,
        nullptr, bmhi, bmlo, 1024,
        16,
        128LL * 4096, 256LL,        // A: +h*128 rows, +s*256 k-offset
        128LL * 4096, 256LL,        // B: same
        128LL, 128LL * 1024,        // C: +h*128 col-offset, +s slab
        cw, 0.08838834764831845f / 256.0f);

    // GC: CT_s = (W1 @ Bm_s)^T -> bf16 split [16][128][512]
    //     A = W1 [512,1024] k=hd1, B = BmT_s [128,1024] k=hd1.
    tc_gemm<2><<<dim3(1, 4, 16), t, SMEM_BYTES>>>(
        w1hi, w1lo, 1024, bmhi, bmlo, 1024, 1024,
        nullptr, cthi, ctlo, 512,
        16,
        0, 0,                        // A: W1 shared
        0, 128LL * 1024,             // B: +s slab
        0, 128LL * 512,              // C: +s slab
        nullptr, 1.0f);

    // GD: out[:, s*128:(s+1)*128] = x @ CT_s^T  (fp32)
    //     A = x [4096,512] k=din, B = CT_s [128,512] k=din.
    tc_gemm<0><<<dim3(1, 32, 16), t, SMEM_BYTES>>>(
        xhi, xlo, 512, cthi, ctlo, 512, 512,
        out, nullptr, nullptr, 2048,
        16,
        0, 0,                        // A: x shared
        0, 128LL * 512,              // B: +s slab
        0, 128LL,                    // C: +s*128 col offset
        nullptr, 1.0f);
}

// round 14
// speedup vs baseline: 2.1829x; 1.0213x over previous
#include <cuda_runtime.h>
#include <cuda_bf16.h>
#include <cstdint>

#define DINL __device__ __forceinline__

// ---------------------------------------------------------------------------
// cseft via mma.sync bf16 hi/lo 3-pass split (base compute_103-safe).
// Factoring (no Q):
//   KT = (y@W2)^T             [1024,4096]  bf16-split
//   VT = (y@W3)^T             [1024,4096]  bf16-split
//   BmT[s][d2][hd1] = cw[h]*c * sum_i KT[hd1, s*256+i] VT[h*128+d2, s*256+i]
//   CT[s][d2][din]  = (W1 @ Bm_s)^T       [16][128][512] bf16-split
//   out[:, s*128:(s+1)*128] = x @ CT_s^T   (fp32)
// All GEMMs: D = A . B^T with A,B K-major.  10.2 GMAC (x3 passes).
// MODE 2 epilogue is smem-staged for coalesced transposed stores.
// ---------------------------------------------------------------------------

// ---------- device scratch ----------
__device__ __nv_bfloat16 g_xhi[4096*512],   g_xlo[4096*512];
__device__ __nv_bfloat16 g_yhi[4096*512],   g_ylo[4096*512];
__device__ __nv_bfloat16 g_w1hi[512*1024],  g_w1lo[512*1024];    // non-transposed
__device__ __nv_bfloat16 g_w2thi[1024*512], g_w2tlo[1024*512];   // transposed
__device__ __nv_bfloat16 g_w3thi[1024*512], g_w3tlo[1024*512];
__device__ __nv_bfloat16 g_kthi[1024*4096], g_ktlo[1024*4096];
__device__ __nv_bfloat16 g_vthi[1024*4096], g_vtlo[1024*4096];
__device__ __nv_bfloat16 g_bmhi[16*128*1024], g_bmlo[16*128*1024];
__device__ __nv_bfloat16 g_cthi[16*128*512],  g_ctlo[16*128*512];

// ---------- helpers ----------
DINL uint32_t smem_u32(const void* p) {
    uint32_t a;
    asm("{ .reg .u64 t; cvta.to.shared.u64 t, %1; cvt.u32.u64 %0, t; }"
        : "=r"(a) : "l"(p));
    return a;
}
DINL void cp16(uint32_t s, const void* g) {
    asm volatile("cp.async.cg.shared.global [%0], [%1], 16;" :: "r"(s), "l"(g));
}
DINL void cp_commit() { asm volatile("cp.async.commit_group;" ::: "memory"); }
DINL void cp_wait1()  { asm volatile("cp.async.wait_group 1;" ::: "memory"); }
DINL void cp_wait0()  { asm volatile("cp.async.wait_group 0;" ::: "memory"); }

DINL void mma16816(float& d0, float& d1, float& d2, float& d3,
                   uint32_t a0, uint32_t a1, uint32_t a2, uint32_t a3,
                   uint32_t b0, uint32_t b1) {
    asm volatile(
        "mma.sync.aligned.m16n8k16.row.col.f32.bf16.bf16.f32 "
        "{%0,%1,%2,%3}, {%4,%5,%6,%7}, {%8,%9}, {%0,%1,%2,%3};"
        : "+f"(d0), "+f"(d1), "+f"(d2), "+f"(d3)
        : "r"(a0), "r"(a1), "r"(a2), "r"(a3), "r"(b0), "r"(b1));
}
DINL uint32_t pack_hi2(float a, float b) {
    __nv_bfloat162 p = __nv_bfloat162(__float2bfloat16(a), __float2bfloat16(b));
    return *(uint32_t*)&p;
}

// ---------- conversion kernels ----------
__global__ void k_split4(const float4* __restrict__ in,
                         uint2* __restrict__ hi, uint2* __restrict__ lo, int n4) {
    for (int i = blockIdx.x * blockDim.x + threadIdx.x; i < n4;
         i += gridDim.x * blockDim.x) {
        float4 v = in[i];
        __nv_bfloat16 h0 = __float2bfloat16(v.x), h1 = __float2bfloat16(v.y);
        __nv_bfloat16 h2 = __float2bfloat16(v.z), h3 = __float2bfloat16(v.w);
        __nv_bfloat162 H0 = __nv_bfloat162(h0, h1), H1 = __nv_bfloat162(h2, h3);
        __nv_bfloat162 L0 = __nv_bfloat162(__float2bfloat16(v.x - __bfloat162float(h0)),
                                           __float2bfloat16(v.y - __bfloat162float(h1)));
        __nv_bfloat162 L1 = __nv_bfloat162(__float2bfloat16(v.z - __bfloat162float(h2)),
                                           __float2bfloat16(v.w - __bfloat162float(h3)));
        hi[i] = make_uint2(*(uint32_t*)&H0, *(uint32_t*)&H1);
        lo[i] = make_uint2(*(uint32_t*)&L0, *(uint32_t*)&L1);
    }
}
__global__ void k_splitT(const float* __restrict__ in,
                         __nv_bfloat16* __restrict__ hiT,
                         __nv_bfloat16* __restrict__ loT, int R, int C) {
    __shared__ float t[32][33];
    const int bx = blockIdx.x * 32;
    const int by = blockIdx.y * 32;
    const int tx = threadIdx.x, ty = threadIdx.y;
#pragma unroll
    for (int i = 0; i < 32; i += 8)
        t[ty + i][tx] = in[(long long)(by + ty + i) * C + bx + tx];
    __syncthreads();
#pragma unroll
    for (int i = 0; i < 32; i += 8) {
        const float v = t[tx][ty + i];
        const __nv_bfloat16 h = __float2bfloat16(v);
        const long long o = (long long)(bx + ty + i) * R + by + tx;
        hiT[o] = h;
        loT[o] = __float2bfloat16(v - __bfloat162float(h));
    }
}

// ---------------------------------------------------------------------------
// HMMA GEMM: C[128,128] tile = sum_K (Ahi Bhi^T + Ahi Blo^T + Alo Bhi^T).
// A [Mtot,Ktot], B [Ntot,Ktot], bf16 K-major. BK = 64, double-buffered cp.async.
// MODE 0: fp32 C.  MODE 1: bf16-split C.  MODE 2: bf16-split C^T (smem-staged).
// ---------------------------------------------------------------------------
#define TILE_B 18432       // 128 * 144 bytes

template <int MODE>
__global__ __launch_bounds__(256) void tc_gemm(
    const __nv_bfloat16* __restrict__ Ahi, const __nv_bfloat16* __restrict__ Alo, int lda,
    const __nv_bfloat16* __restrict__ Bhi, const __nv_bfloat16* __restrict__ Blo, int ldb,
    int Ktot,
    float* __restrict__ Cf, __nv_bfloat16* __restrict__ Chi,
    __nv_bfloat16* __restrict__ Clo, int ldc,
    int zdiv,
    long long aOff1, long long aOff2, long long bOff1, long long bOff2,
    long long cOff1, long long cOff2,
    const float* __restrict__ swp, float sfac)
{
    extern __shared__ char sm[];
    const uint32_t smb = smem_u32(sm);

    const int tid = threadIdx.x;
    const int wid = tid >> 5;
    const int lane = tid & 31;
    const int g = lane >> 2;       // 0..7
    const int tig = lane & 3;      // 0..3
    const int wm = wid & 1;        // m half
    const int wn = wid >> 1;       // n quarter

    const int z = blockIdx.z;
    const int z1 = z / zdiv, z2 = z % zdiv;
    const long long offA = (long long)z1 * aOff1 + (long long)z2 * aOff2;
    const long long offB = (long long)z1 * bOff1 + (long long)z2 * bOff2;
    const long long offC = (long long)z1 * cOff1 + (long long)z2 * cOff2;
    const float scale = sfac * (swp ? swp[z1] : 1.0f);

    const int rowBase = blockIdx.y * 128;
    const int colBase = blockIdx.x * 128;

    const __nv_bfloat16* pA[2] = { Ahi + offA + (long long)rowBase * lda,
                                   Alo + offA + (long long)rowBase * lda };
    const __nv_bfloat16* pB[2] = { Bhi + offB + (long long)colBase * ldb,
                                   Blo + offB + (long long)colBase * ldb };

    auto load_chunk = [&](int buf, int k0) {
        const uint32_t base = smb + (uint32_t)buf * (4 * TILE_B);
#pragma unroll
        for (int i = 0; i < 4; ++i) {
            const int idx = tid + (i << 8);
            const int r = idx >> 3, j = idx & 7;
            const uint32_t so = (uint32_t)(r * 144 + j * 16);
            const long long ga = (long long)r * lda + k0 + j * 8;
            const long long gb = (long long)r * ldb + k0 + j * 8;
            cp16(base + so,              pA[0] + ga);
            cp16(base + TILE_B + so,     pA[1] + ga);
            cp16(base + 2 * TILE_B + so, pB[0] + gb);
            cp16(base + 3 * TILE_B + so, pB[1] + gb);
        }
        cp_commit();
    };

    float acc[4][4][4];
#pragma unroll
    for (int i = 0; i < 4; ++i)
#pragma unroll
        for (int j = 0; j < 4; ++j)
#pragma unroll
            for (int q = 0; q < 4; ++q) acc[i][j][q] = 0.0f;

    const int nchunks = Ktot >> 6;
    load_chunk(0, 0);

    for (int c = 0; c < nchunks; ++c) {
        if (c + 1 < nchunks) {
            load_chunk((c + 1) & 1, (c + 1) << 6);
            cp_wait1();
        } else {
            cp_wait0();
        }
        __syncthreads();

        const uint32_t bufb = smb + (uint32_t)(c & 1) * (4 * TILE_B);

#pragma unroll
        for (int pass = 0; pass < 3; ++pass) {
            const uint32_t sA = bufb + (pass == 2 ? TILE_B : 0);
            const uint32_t sB = bufb + 2 * TILE_B + (pass == 1 ? TILE_B : 0);

#pragma unroll
            for (int ks = 0; ks < 4; ++ks) {
                uint32_t a[4][4], b[4][2];
#pragma unroll
                for (int mi = 0; mi < 4; ++mi) {
                    const int r0 = wm * 64 + mi * 16 + g;
                    const uint32_t w0 = sA + (uint32_t)(r0 * 144) + (uint32_t)((ks * 8 + tig) * 4);
                    const uint32_t w1 = w0 + 8 * 144;
                    asm volatile("ld.shared.b32 %0, [%1];" : "=r"(a[mi][0]) : "r"(w0));
                    asm volatile("ld.shared.b32 %0, [%1];" : "=r"(a[mi][1]) : "r"(w1));
                    asm volatile("ld.shared.b32 %0, [%1];" : "=r"(a[mi][2]) : "r"(w0 + 16));
                    asm volatile("ld.shared.b32 %0, [%1];" : "=r"(a[mi][3]) : "r"(w1 + 16));
                }
#pragma unroll
                for (int ni = 0; ni < 4; ++ni) {
                    const int rn = wn * 32 + ni * 8 + g;
                    const uint32_t w0 = sB + (uint32_t)(rn * 144) + (uint32_t)((ks * 8 + tig) * 4);
                    asm volatile("ld.shared.b32 %0, [%1];" : "=r"(b[ni][0]) : "r"(w0));
                    asm volatile("ld.shared.b32 %0, [%1];" : "=r"(b[ni][1]) : "r"(w0 + 16));
                }
#pragma unroll
                for (int mi = 0; mi < 4; ++mi)
#pragma unroll
                    for (int ni = 0; ni < 4; ++ni)
                        mma16816(acc[mi][ni][0], acc[mi][ni][1],
                                 acc[mi][ni][2], acc[mi][ni][3],
                                 a[mi][0], a[mi][1], a[mi][2], a[mi][3],
                                 b[ni][0], b[ni][1]);
            }
        }
        __syncthreads();
    }

    // ---- epilogue ----
    if (MODE == 2) {
        // Stage C^T into smem fp32 [128 n][132 m], then coalesced split-store.
        float* T = (float*)sm;   // smem is dead after the final __syncthreads()
#pragma unroll
        for (int mi = 0; mi < 4; ++mi) {
            const int rl = wm * 64 + mi * 16 + g;
#pragma unroll
            for (int ni = 0; ni < 4; ++ni) {
                const int cl = wn * 32 + ni * 8 + tig * 2;
                T[cl * 132 + rl]           = acc[mi][ni][0] * scale;
                T[(cl + 1) * 132 + rl]     = acc[mi][ni][1] * scale;
                T[cl * 132 + rl + 8]       = acc[mi][ni][2] * scale;
                T[(cl + 1) * 132 + rl + 8] = acc[mi][ni][3] * scale;
            }
        }
        __syncthreads();
        // Each thread: one 64-float segment of one output row (n = out row).
        const int n = tid >> 1;
        const int mb = (tid & 1) * 64;
        const float* Tr = T + n * 132 + mb;
        __nv_bfloat16* Hp = Chi + offC + (long long)(colBase + n) * ldc + rowBase + mb;
        __nv_bfloat16* Lp = Clo + offC + (long long)(colBase + n) * ldc + rowBase + mb;
#pragma unroll
        for (int gp = 0; gp < 8; ++gp) {
            float v[8];
#pragma unroll
            for (int j = 0; j < 8; ++j) v[j] = Tr[gp * 8 + j];
            uint32_t H[4], L[4];
#pragma unroll
            for (int j = 0; j < 4; ++j) {
                const float a0 = v[2 * j], a1 = v[2 * j + 1];
                H[j] = pack_hi2(a0, a1);
                const __nv_bfloat162* hp = (const __nv_bfloat162*)&H[j];
                L[j] = pack_hi2(a0 - __bfloat162float(hp->x),
                                a1 - __bfloat162float(hp->y));
            }
            *(uint4*)(Hp + gp * 8) = *(uint4*)H;
            *(uint4*)(Lp + gp * 8) = *(uint4*)L;
        }
        return;
    }

#pragma unroll
    for (int mi = 0; mi < 4; ++mi) {
        const long long r0 = rowBase + wm * 64 + mi * 16 + g;
        const long long r1 = r0 + 8;
#pragma unroll
        for (int ni = 0; ni < 4; ++ni) {
            const long long col = colBase + wn * 32 + ni * 8 + tig * 2;
            const float v00 = acc[mi][ni][0] * scale;
            const float v01 = acc[mi][ni][1] * scale;
            const float v10 = acc[mi][ni][2] * scale;
            const float v11 = acc[mi][ni][3] * scale;

            if (MODE == 0) {
                *(float2*)(Cf + offC + r0 * ldc + col) = make_float2(v00, v01);
                *(float2*)(Cf + offC + r1 * ldc + col) = make_float2(v10, v11);
            } else {   // MODE 1
                __nv_bfloat16 h00 = __float2bfloat16(v00);
                __nv_bfloat16 h01 = __float2bfloat16(v01);
                __nv_bfloat16 h10 = __float2bfloat16(v10);
                __nv_bfloat16 h11 = __float2bfloat16(v11);
                *(__nv_bfloat162*)(Chi + offC + r0 * ldc + col) = __nv_bfloat162(h00, h01);
                *(__nv_bfloat162*)(Chi + offC + r1 * ldc + col) = __nv_bfloat162(h10, h11);
                *(__nv_bfloat162*)(Clo + offC + r0 * ldc + col) =
                    __nv_bfloat162(__float2bfloat16(v00 - __bfloat162float(h00)),
                                   __float2bfloat16(v01 - __bfloat162float(h01)));
                *(__nv_bfloat162*)(Clo + offC + r1 * ldc + col) =
                    __nv_bfloat162(__float2bfloat16(v10 - __bfloat162float(h10)),
                                   __float2bfloat16(v11 - __bfloat162float(h11)));
            }
        }
    }
}

// ---------------------------------------------------------------------------
extern "C" void kernel_launch(void* const* d_in, const int* in_sizes, int n_in,
                              void* d_out, int out_size)
{
    const float* x  = (const float*)d_in[0];   // [4096, 512]
    const float* y  = (const float*)d_in[1];   // [4096, 512]
    const float* W1 = (const float*)d_in[2];   // [512, 1024]
    const float* W2 = (const float*)d_in[3];   // [512, 1024]
    const float* W3 = (const float*)d_in[4];   // [512, 1024]
    const float* cw = (const float*)d_in[5];   // [8]
    float* out = (float*)d_out;                // [4096, 2048]

    __nv_bfloat16 *xhi, *xlo, *yhi, *ylo;
    __nv_bfloat16 *w1hi, *w1lo, *w2thi, *w2tlo, *w3thi, *w3tlo;
    __nv_bfloat16 *kthi, *ktlo, *vthi, *vtlo, *bmhi, *bmlo, *cthi, *ctlo;
    cudaGetSymbolAddress((void**)&xhi, g_xhi);     cudaGetSymbolAddress((void**)&xlo, g_xlo);
    cudaGetSymbolAddress((void**)&yhi, g_yhi);     cudaGetSymbolAddress((void**)&ylo, g_ylo);
    cudaGetSymbolAddress((void**)&w1hi, g_w1hi);   cudaGetSymbolAddress((void**)&w1lo, g_w1lo);
    cudaGetSymbolAddress((void**)&w2thi, g_w2thi); cudaGetSymbolAddress((void**)&w2tlo, g_w2tlo);
    cudaGetSymbolAddress((void**)&w3thi, g_w3thi); cudaGetSymbolAddress((void**)&w3tlo, g_w3tlo);
    cudaGetSymbolAddress((void**)&kthi, g_kthi);   cudaGetSymbolAddress((void**)&ktlo, g_ktlo);
    cudaGetSymbolAddress((void**)&vthi, g_vthi);   cudaGetSymbolAddress((void**)&vtlo, g_vtlo);
    cudaGetSymbolAddress((void**)&bmhi, g_bmhi);   cudaGetSymbolAddress((void**)&bmlo, g_bmlo);
    cudaGetSymbolAddress((void**)&cthi, g_cthi);   cudaGetSymbolAddress((void**)&ctlo, g_ctlo);

    const int SMEM_BYTES = 2 * 4 * TILE_B;   // 147456 (>= 128*132*4 staging)
    cudaFuncSetAttribute(tc_gemm<0>, cudaFuncAttributeMaxDynamicSharedMemorySize, SMEM_BYTES);
    cudaFuncSetAttribute(tc_gemm<1>, cudaFuncAttributeMaxDynamicSharedMemorySize, SMEM_BYTES);
    cudaFuncSetAttribute(tc_gemm<2>, cudaFuncAttributeMaxDynamicSharedMemorySize, SMEM_BYTES);

    dim3 t(256);

    // --- conversions ---
    k_split4<<<1024, 256>>>((const float4*)x, (uint2*)xhi, (uint2*)xlo, 4096 * 512 / 4);
    k_split4<<<1024, 256>>>((const float4*)y, (uint2*)yhi, (uint2*)ylo, 4096 * 512 / 4);
    k_split4<<<512, 256>>>((const float4*)W1, (uint2*)w1hi, (uint2*)w1lo, 512 * 1024 / 4);
    k_splitT<<<dim3(32, 16), dim3(32, 8)>>>(W2, w2thi, w2tlo, 512, 1024);
    k_splitT<<<dim3(32, 16), dim3(32, 8)>>>(W3, w3thi, w3tlo, 512, 1024);

    // G2: KT = (y@W2)^T -> bf16 split [1024,4096]
    tc_gemm<2><<<dim3(8, 32, 1), t, SMEM_BYTES>>>(
        yhi, ylo, 512, w2thi, w2tlo, 512, 512,
        nullptr, kthi, ktlo, 4096,
        1, 0, 0, 0, 0, 0, 0, nullptr, 1.0f);

    // G3: VT = (y@W3)^T -> bf16 split [1024,4096]
    tc_gemm<2><<<dim3(8, 32, 1), t, SMEM_BYTES>>>(
        yhi, ylo, 512, w3thi, w3tlo, 512, 512,
        nullptr, vthi, vtlo, 4096,
        1, 0, 0, 0, 0, 0, 0, nullptr, 1.0f);

    // G4: per z = h*16+s: D[d1,d2] = KT[h*128+d1, s*256+:256] . VT[h*128+d2, ...]^T
    //     scaled by cw[h]*inv_sqrt/256, stored transposed: BmT[s][d2][h*128+d1]
    tc_gemm<2><<<dim3(1, 1, 128), t, SMEM_BYTES>>>(
        kthi, ktlo, 4096, vthi, vtlo, 4096, 256,
        nullptr, bmhi, bmlo, 1024,
        16,
        128LL * 4096, 256LL,        // A: +h*128 rows, +s*256 k-offset
        128LL * 4096, 256LL,        // B: same
        128LL, 128LL * 1024,        // C: +h*128 col-offset, +s slab
        cw, 0.08838834764831845f / 256.0f);

    // GC: CT_s = (W1 @ Bm_s)^T -> bf16 split [16][128][512]
    tc_gemm<2><<<dim3(1, 4, 16), t, SMEM_BYTES>>>(
        w1hi, w1lo, 1024, bmhi, bmlo, 1024, 1024,
        nullptr, cthi, ctlo, 512,
        16,
        0, 0,                        // A: W1 shared
        0, 128LL * 1024,             // B: +s slab
        0, 128LL * 512,              // C: +s slab
        nullptr, 1.0f);

    // GD: out[:, s*128:(s+1)*128] = x @ CT_s^T  (fp32)
    tc_gemm<0><<<dim3(1, 32, 16), t, SMEM_BYTES>>>(
        xhi, xlo, 512, cthi, ctlo, 512, 512,
        out, nullptr, nullptr, 2048,
        16,
        0, 0,                        // A: x shared
        0, 128LL * 512,              // B: +s slab
        0, 128LL,                    // C: +s*128 col offset
        nullptr, 1.0f);
}

// round 15
// speedup vs baseline: 2.2727x; 1.0412x over previous
#include <cuda_runtime.h>
#include <cuda_bf16.h>
#include <cstdint>

#define DINL __device__ __forceinline__

// ---------------------------------------------------------------------------
// cseft via mma.sync bf16 hi/lo 3-pass split (base compute_103-safe).
// Factoring (no Q):
//   KT = (y@W2)^T             [1024,4096]  bf16-split
//   VT = (y@W3)^T             [1024,4096]  bf16-split
//   BmT[s][d2][hd1] = cw[h]*c * sum_i KT[hd1, s*256+i] VT[h*128+d2, s*256+i]
//   CT[s][d2][din]  = (W1 @ Bm_s)^T       [16][128][512] bf16-split
//   out[:, s*128:(s+1)*128] = x @ CT_s^T   (fp32)
// All GEMMs: D = A . B^T with A,B K-major.  10.2 GMAC (x3 passes).
// Mainloop: ldmatrix fragment loads + hi/lo fragment reuse across passes.
// ---------------------------------------------------------------------------

// ---------- device scratch ----------
__device__ __nv_bfloat16 g_xhi[4096*512],   g_xlo[4096*512];
__device__ __nv_bfloat16 g_yhi[4096*512],   g_ylo[4096*512];
__device__ __nv_bfloat16 g_w1hi[512*1024],  g_w1lo[512*1024];    // non-transposed
__device__ __nv_bfloat16 g_w2thi[1024*512], g_w2tlo[1024*512];   // transposed
__device__ __nv_bfloat16 g_w3thi[1024*512], g_w3tlo[1024*512];
__device__ __nv_bfloat16 g_kthi[1024*4096], g_ktlo[1024*4096];
__device__ __nv_bfloat16 g_vthi[1024*4096], g_vtlo[1024*4096];
__device__ __nv_bfloat16 g_bmhi[16*128*1024], g_bmlo[16*128*1024];
__device__ __nv_bfloat16 g_cthi[16*128*512],  g_ctlo[16*128*512];

// ---------- helpers ----------
DINL uint32_t smem_u32(const void* p) {
    uint32_t a;
    asm("{ .reg .u64 t; cvta.to.shared.u64 t, %1; cvt.u32.u64 %0, t; }"
        : "=r"(a) : "l"(p));
    return a;
}
DINL void cp16(uint32_t s, const void* g) {
    asm volatile("cp.async.cg.shared.global [%0], [%1], 16;" :: "r"(s), "l"(g));
}
DINL void cp_commit() { asm volatile("cp.async.commit_group;" ::: "memory"); }
DINL void cp_wait1()  { asm volatile("cp.async.wait_group 1;" ::: "memory"); }
DINL void cp_wait0()  { asm volatile("cp.async.wait_group 0;" ::: "memory"); }

DINL void mma16816(float& d0, float& d1, float& d2, float& d3,
                   uint32_t a0, uint32_t a1, uint32_t a2, uint32_t a3,
                   uint32_t b0, uint32_t b1) {
    asm volatile(
        "mma.sync.aligned.m16n8k16.row.col.f32.bf16.bf16.f32 "
        "{%0,%1,%2,%3}, {%4,%5,%6,%7}, {%8,%9}, {%0,%1,%2,%3};"
        : "+f"(d0), "+f"(d1), "+f"(d2), "+f"(d3)
        : "r"(a0), "r"(a1), "r"(a2), "r"(a3), "r"(b0), "r"(b1));
}
DINL void ldsm4(uint32_t& r0, uint32_t& r1, uint32_t& r2, uint32_t& r3, uint32_t a) {
    asm volatile("ldmatrix.sync.aligned.m8n8.x4.shared.b16 {%0,%1,%2,%3}, [%4];"
                 : "=r"(r0), "=r"(r1), "=r"(r2), "=r"(r3) : "r"(a));
}
DINL uint32_t pack_hi2(float a, float b) {
    __nv_bfloat162 p = __nv_bfloat162(__float2bfloat16(a), __float2bfloat16(b));
    return *(uint32_t*)&p;
}

// ---------- conversion kernels ----------
__global__ void k_split4(const float4* __restrict__ in,
                         uint2* __restrict__ hi, uint2* __restrict__ lo, int n4) {
    for (int i = blockIdx.x * blockDim.x + threadIdx.x; i < n4;
         i += gridDim.x * blockDim.x) {
        float4 v = in[i];
        __nv_bfloat16 h0 = __float2bfloat16(v.x), h1 = __float2bfloat16(v.y);
        __nv_bfloat16 h2 = __float2bfloat16(v.z), h3 = __float2bfloat16(v.w);
        __nv_bfloat162 H0 = __nv_bfloat162(h0, h1), H1 = __nv_bfloat162(h2, h3);
        __nv_bfloat162 L0 = __nv_bfloat162(__float2bfloat16(v.x - __bfloat162float(h0)),
                                           __float2bfloat16(v.y - __bfloat162float(h1)));
        __nv_bfloat162 L1 = __nv_bfloat162(__float2bfloat16(v.z - __bfloat162float(h2)),
                                           __float2bfloat16(v.w - __bfloat162float(h3)));
        hi[i] = make_uint2(*(uint32_t*)&H0, *(uint32_t*)&H1);
        lo[i] = make_uint2(*(uint32_t*)&L0, *(uint32_t*)&L1);
    }
}
__global__ void k_splitT(const float* __restrict__ in,
                         __nv_bfloat16* __restrict__ hiT,
                         __nv_bfloat16* __restrict__ loT, int R, int C) {
    __shared__ float t[32][33];
    const int bx = blockIdx.x * 32;
    const int by = blockIdx.y * 32;
    const int tx = threadIdx.x, ty = threadIdx.y;
#pragma unroll
    for (int i = 0; i < 32; i += 8)
        t[ty + i][tx] = in[(long long)(by + ty + i) * C + bx + tx];
    __syncthreads();
#pragma unroll
    for (int i = 0; i < 32; i += 8) {
        const float v = t[tx][ty + i];
        const __nv_bfloat16 h = __float2bfloat16(v);
        const long long o = (long long)(bx + ty + i) * R + by + tx;
        hiT[o] = h;
        loT[o] = __float2bfloat16(v - __bfloat162float(h));
    }
}

// ---------------------------------------------------------------------------
// HMMA GEMM: C[128,128] tile = sum_K (Ahi Bhi^T + Ahi Blo^T + Alo Bhi^T).
// A [Mtot,Ktot], B [Ntot,Ktot], bf16 K-major. BK = 64, double-buffered cp.async.
// ldmatrix fragment loads; hi/lo fragments loaded once per k-step, used by
// all 3 passes (48 HMMA per k-step per warp, 12 LDSM).
// MODE 0: fp32 C.  MODE 1: bf16-split C.  MODE 2: bf16-split C^T (smem-staged).
// ---------------------------------------------------------------------------
#define TILE_B 18432       // 128 * 144 bytes

template <int MODE>
__global__ __launch_bounds__(256) void tc_gemm(
    const __nv_bfloat16* __restrict__ Ahi, const __nv_bfloat16* __restrict__ Alo, int lda,
    const __nv_bfloat16* __restrict__ Bhi, const __nv_bfloat16* __restrict__ Blo, int ldb,
    int Ktot,
    float* __restrict__ Cf, __nv_bfloat16* __restrict__ Chi,
    __nv_bfloat16* __restrict__ Clo, int ldc,
    int zdiv,
    long long aOff1, long long aOff2, long long bOff1, long long bOff2,
    long long cOff1, long long cOff2,
    const float* __restrict__ swp, float sfac)
{
    extern __shared__ char sm[];
    const uint32_t smb = smem_u32(sm);

    const int tid = threadIdx.x;
    const int wid = tid >> 5;
    const int lane = tid & 31;
    const int g = lane >> 2;       // 0..7
    const int tig = lane & 3;      // 0..3
    const int wm = wid & 1;        // m half
    const int wn = wid >> 1;       // n quarter

    const int z = blockIdx.z;
    const int z1 = z / zdiv, z2 = z % zdiv;
    const long long offA = (long long)z1 * aOff1 + (long long)z2 * aOff2;
    const long long offB = (long long)z1 * bOff1 + (long long)z2 * bOff2;
    const long long offC = (long long)z1 * cOff1 + (long long)z2 * cOff2;
    const float scale = sfac * (swp ? swp[z1] : 1.0f);

    const int rowBase = blockIdx.y * 128;
    const int colBase = blockIdx.x * 128;

    const __nv_bfloat16* pA[2] = { Ahi + offA + (long long)rowBase * lda,
                                   Alo + offA + (long long)rowBase * lda };
    const __nv_bfloat16* pB[2] = { Bhi + offB + (long long)colBase * ldb,
                                   Blo + offB + (long long)colBase * ldb };

    auto load_chunk = [&](int buf, int k0) {
        const uint32_t base = smb + (uint32_t)buf * (4 * TILE_B);
#pragma unroll
        for (int i = 0; i < 4; ++i) {
            const int idx = tid + (i << 8);
            const int r = idx >> 3, j = idx & 7;
            const uint32_t so = (uint32_t)(r * 144 + j * 16);
            const long long ga = (long long)r * lda + k0 + j * 8;
            const long long gb = (long long)r * ldb + k0 + j * 8;
            cp16(base + so,              pA[0] + ga);
            cp16(base + TILE_B + so,     pA[1] + ga);
            cp16(base + 2 * TILE_B + so, pB[0] + gb);
            cp16(base + 3 * TILE_B + so, pB[1] + gb);
        }
        cp_commit();
    };

    // ldmatrix lane-dependent offsets (bytes within a tile).
    // A x4: row = lane & 15, k-block byte = (lane >> 4) * 16.
    const uint32_t aLOff = (uint32_t)((lane & 15) * 144 + (lane >> 4) * 16);
    // B x4 (two n8 tiles): n-row = (lane>>4)*8 + (lane&7), k-block = ((lane>>3)&1)*16.
    const uint32_t bLOff = (uint32_t)((((lane >> 4) * 8) + (lane & 7)) * 144 +
                                      ((lane >> 3) & 1) * 16);
    const uint32_t aWarp = (uint32_t)(wm * 64 * 144);
    const uint32_t bWarp = (uint32_t)(wn * 32 * 144);

    float acc[4][4][4];
#pragma unroll
    for (int i = 0; i < 4; ++i)
#pragma unroll
        for (int j = 0; j < 4; ++j)
#pragma unroll
            for (int q = 0; q < 4; ++q) acc[i][j][q] = 0.0f;

    const int nchunks = Ktot >> 6;
    load_chunk(0, 0);

    for (int c = 0; c < nchunks; ++c) {
        if (c + 1 < nchunks) {
            load_chunk((c + 1) & 1, (c + 1) << 6);
            cp_wait1();
        } else {
            cp_wait0();
        }
        __syncthreads();

        const uint32_t bufb = smb + (uint32_t)(c & 1) * (4 * TILE_B);
        const uint32_t sAH = bufb + aWarp + aLOff;
        const uint32_t sAL = sAH + TILE_B;
        const uint32_t sBH = bufb + 2 * TILE_B + bWarp + bLOff;
        const uint32_t sBL = sBH + TILE_B;

#pragma unroll
        for (int ks = 0; ks < 4; ++ks) {
            const uint32_t kb = (uint32_t)(ks * 32);
            uint32_t aH[4][4], aL[4][4], bH[4][2], bL[4][2];
#pragma unroll
            for (int mi = 0; mi < 4; ++mi) {
                ldsm4(aH[mi][0], aH[mi][1], aH[mi][2], aH[mi][3],
                      sAH + (uint32_t)(mi * 16 * 144) + kb);
                ldsm4(aL[mi][0], aL[mi][1], aL[mi][2], aL[mi][3],
                      sAL + (uint32_t)(mi * 16 * 144) + kb);
            }
#pragma unroll
            for (int nj = 0; nj < 2; ++nj) {
                ldsm4(bH[2*nj][0], bH[2*nj][1], bH[2*nj+1][0], bH[2*nj+1][1],
                      sBH + (uint32_t)(nj * 16 * 144) + kb);
                ldsm4(bL[2*nj][0], bL[2*nj][1], bL[2*nj+1][0], bL[2*nj+1][1],
                      sBL + (uint32_t)(nj * 16 * 144) + kb);
            }
            // pass 0: Ahi x Bhi
#pragma unroll
            for (int mi = 0; mi < 4; ++mi)
#pragma unroll
                for (int ni = 0; ni < 4; ++ni)
                    mma16816(acc[mi][ni][0], acc[mi][ni][1], acc[mi][ni][2], acc[mi][ni][3],
                             aH[mi][0], aH[mi][1], aH[mi][2], aH[mi][3],
                             bH[ni][0], bH[ni][1]);
            // pass 1: Ahi x Blo
#pragma unroll
            for (int mi = 0; mi < 4; ++mi)
#pragma unroll
                for (int ni = 0; ni < 4; ++ni)
                    mma16816(acc[mi][ni][0], acc[mi][ni][1], acc[mi][ni][2], acc[mi][ni][3],
                             aH[mi][0], aH[mi][1], aH[mi][2], aH[mi][3],
                             bL[ni][0], bL[ni][1]);
            // pass 2: Alo x Bhi
#pragma unroll
            for (int mi = 0; mi < 4; ++mi)
#pragma unroll
                for (int ni = 0; ni < 4; ++ni)
                    mma16816(acc[mi][ni][0], acc[mi][ni][1], acc[mi][ni][2], acc[mi][ni][3],
                             aL[mi][0], aL[mi][1], aL[mi][2], aL[mi][3],
                             bH[ni][0], bH[ni][1]);
        }
        __syncthreads();
    }

    // ---- epilogue ----
    if (MODE == 2) {
        // Stage C^T into smem fp32 [128 n][132 m], then coalesced split-store.
        float* T = (float*)sm;
#pragma unroll
        for (int mi = 0; mi < 4; ++mi) {
            const int rl = wm * 64 + mi * 16 + g;
#pragma unroll
            for (int ni = 0; ni < 4; ++ni) {
                const int cl = wn * 32 + ni * 8 + tig * 2;
                T[cl * 132 + rl]           = acc[mi][ni][0] * scale;
                T[(cl + 1) * 132 + rl]     = acc[mi][ni][1] * scale;
                T[cl * 132 + rl + 8]       = acc[mi][ni][2] * scale;
                T[(cl + 1) * 132 + rl + 8] = acc[mi][ni][3] * scale;
            }
        }
        __syncthreads();
        const int n = tid >> 1;
        const int mb = (tid & 1) * 64;
        const float* Tr = T + n * 132 + mb;
        __nv_bfloat16* Hp = Chi + offC + (long long)(colBase + n) * ldc + rowBase + mb;
        __nv_bfloat16* Lp = Clo + offC + (long long)(colBase + n) * ldc + rowBase + mb;
#pragma unroll
        for (int gp = 0; gp < 8; ++gp) {
            float v[8];
#pragma unroll
            for (int j = 0; j < 8; ++j) v[j] = Tr[gp * 8 + j];
            uint32_t H[4], L[4];
#pragma unroll
            for (int j = 0; j < 4; ++j) {
                const float a0 = v[2 * j], a1 = v[2 * j + 1];
                H[j] = pack_hi2(a0, a1);
                const __nv_bfloat162* hp = (const __nv_bfloat162*)&H[j];
                L[j] = pack_hi2(a0 - __bfloat162float(hp->x),
                                a1 - __bfloat162float(hp->y));
            }
            *(uint4*)(Hp + gp * 8) = *(uint4*)H;
            *(uint4*)(Lp + gp * 8) = *(uint4*)L;
        }
        return;
    }

#pragma unroll
    for (int mi = 0; mi < 4; ++mi) {
        const long long r0 = rowBase + wm * 64 + mi * 16 + g;
        const long long r1 = r0 + 8;
#pragma unroll
        for (int ni = 0; ni < 4; ++ni) {
            const long long col = colBase + wn * 32 + ni * 8 + tig * 2;
            const float v00 = acc[mi][ni][0] * scale;
            const float v01 = acc[mi][ni][1] * scale;
            const float v10 = acc[mi][ni][2] * scale;
            const float v11 = acc[mi][ni][3] * scale;

            if (MODE == 0) {
                *(float2*)(Cf + offC + r0 * ldc + col) = make_float2(v00, v01);
                *(float2*)(Cf + offC + r1 * ldc + col) = make_float2(v10, v11);
            } else {   // MODE 1
                __nv_bfloat16 h00 = __float2bfloat16(v00);
                __nv_bfloat16 h01 = __float2bfloat16(v01);
                __nv_bfloat16 h10 = __float2bfloat16(v10);
                __nv_bfloat16 h11 = __float2bfloat16(v11);
                *(__nv_bfloat162*)(Chi + offC + r0 * ldc + col) = __nv_bfloat162(h00, h01);
                *(__nv_bfloat162*)(Chi + offC + r1 * ldc + col) = __nv_bfloat162(h10, h11);
                *(__nv_bfloat162*)(Clo + offC + r0 * ldc + col) =
                    __nv_bfloat162(__float2bfloat16(v00 - __bfloat162float(h00)),
                                   __float2bfloat16(v01 - __bfloat162float(h01)));
                *(__nv_bfloat162*)(Clo + offC + r1 * ldc + col) =
                    __nv_bfloat162(__float2bfloat16(v10 - __bfloat162float(h10)),
                                   __float2bfloat16(v11 - __bfloat162float(h11)));
            }
        }
    }
}

// ---------------------------------------------------------------------------
extern "C" void kernel_launch(void* const* d_in, const int* in_sizes, int n_in,
                              void* d_out, int out_size)
{
    const float* x  = (const float*)d_in[0];   // [4096, 512]
    const float* y  = (const float*)d_in[1];   // [4096, 512]
    const float* W1 = (const float*)d_in[2];   // [512, 1024]
    const float* W2 = (const float*)d_in[3];   // [512, 1024]
    const float* W3 = (const float*)d_in[4];   // [512, 1024]
    const float* cw = (const float*)d_in[5];   // [8]
    float* out = (float*)d_out;                // [4096, 2048]

    __nv_bfloat16 *xhi, *xlo, *yhi, *ylo;
    __nv_bfloat16 *w1hi, *w1lo, *w2thi, *w2tlo, *w3thi, *w3tlo;
    __nv_bfloat16 *kthi, *ktlo, *vthi, *vtlo, *bmhi, *bmlo, *cthi, *ctlo;
    cudaGetSymbolAddress((void**)&xhi, g_xhi);     cudaGetSymbolAddress((void**)&xlo, g_xlo);
    cudaGetSymbolAddress((void**)&yhi, g_yhi);     cudaGetSymbolAddress((void**)&ylo, g_ylo);
    cudaGetSymbolAddress((void**)&w1hi, g_w1hi);   cudaGetSymbolAddress((void**)&w1lo, g_w1lo);
    cudaGetSymbolAddress((void**)&w2thi, g_w2thi); cudaGetSymbolAddress((void**)&w2tlo, g_w2tlo);
    cudaGetSymbolAddress((void**)&w3thi, g_w3thi); cudaGetSymbolAddress((void**)&w3tlo, g_w3tlo);
    cudaGetSymbolAddress((void**)&kthi, g_kthi);   cudaGetSymbolAddress((void**)&ktlo, g_ktlo);
    cudaGetSymbolAddress((void**)&vthi, g_vthi);   cudaGetSymbolAddress((void**)&vtlo, g_vtlo);
    cudaGetSymbolAddress((void**)&bmhi, g_bmhi);   cudaGetSymbolAddress((void**)&bmlo, g_bmlo);
    cudaGetSymbolAddress((void**)&cthi, g_cthi);   cudaGetSymbolAddress((void**)&ctlo, g_ctlo);

    const int SMEM_BYTES = 2 * 4 * TILE_B;   // 147456 (>= 128*132*4 staging)
    cudaFuncSetAttribute(tc_gemm<0>, cudaFuncAttributeMaxDynamicSharedMemorySize, SMEM_BYTES);
    cudaFuncSetAttribute(tc_gemm<1>, cudaFuncAttributeMaxDynamicSharedMemorySize, SMEM_BYTES);
    cudaFuncSetAttribute(tc_gemm<2>, cudaFuncAttributeMaxDynamicSharedMemorySize, SMEM_BYTES);

    dim3 t(256);

    // --- conversions ---
    k_split4<<<1024, 256>>>((const float4*)x, (uint2*)xhi, (uint2*)xlo, 4096 * 512 / 4);
    k_split4<<<1024, 256>>>((const float4*)y, (uint2*)yhi, (uint2*)ylo, 4096 * 512 / 4);
    k_split4<<<512, 256>>>((const float4*)W1, (uint2*)w1hi, (uint2*)w1lo, 512 * 1024 / 4);
    k_splitT<<<dim3(32, 16), dim3(32, 8)>>>(W2, w2thi, w2tlo, 512, 1024);
    k_splitT<<<dim3(32, 16), dim3(32, 8)>>>(W3, w3thi, w3tlo, 512, 1024);

    // G2: KT = (y@W2)^T -> bf16 split [1024,4096]
    tc_gemm<2><<<dim3(8, 32, 1), t, SMEM_BYTES>>>(
        yhi, ylo, 512, w2thi, w2tlo, 512, 512,
        nullptr, kthi, ktlo, 4096,
        1, 0, 0, 0, 0, 0, 0, nullptr, 1.0f);

    // G3: VT = (y@W3)^T -> bf16 split [1024,4096]
    tc_gemm<2><<<dim3(8, 32, 1), t, SMEM_BYTES>>>(
        yhi, ylo, 512, w3thi, w3tlo, 512, 512,
        nullptr, vthi, vtlo, 4096,
        1, 0, 0, 0, 0, 0, 0, nullptr, 1.0f);

    // G4: per z = h*16+s: D[d1,d2] = KT[h*128+d1, s*256+:256] . VT[h*128+d2, ...]^T
    //     scaled by cw[h]*inv_sqrt/256, stored transposed: BmT[s][d2][h*128+d1]
    tc_gemm<2><<<dim3(1, 1, 128), t, SMEM_BYTES>>>(
        kthi, ktlo, 4096, vthi, vtlo, 4096, 256,
        nullptr, bmhi, bmlo, 1024,
        16,
        128LL * 4096, 256LL,        // A: +h*128 rows, +s*256 k-offset
        128LL * 4096, 256LL,        // B: same
        128LL, 128LL * 1024,        // C: +h*128 col-offset, +s slab
        cw, 0.08838834764831845f / 256.0f);

    // GC: CT_s = (W1 @ Bm_s)^T -> bf16 split [16][128][512]
    tc_gemm<2><<<dim3(1, 4, 16), t, SMEM_BYTES>>>(
        w1hi, w1lo, 1024, bmhi, bmlo, 1024, 1024,
        nullptr, cthi, ctlo, 512,
        16,
        0, 0,                        // A: W1 shared
        0, 128LL * 1024,             // B: +s slab
        0, 128LL * 512,              // C: +s slab
        nullptr, 1.0f);

    // GD: out[:, s*128:(s+1)*128] = x @ CT_s^T  (fp32)
    tc_gemm<0><<<dim3(1, 32, 16), t, SMEM_BYTES>>>(
        xhi, xlo, 512, cthi, ctlo, 512, 512,
        out, nullptr, nullptr, 2048,
        16,
        0, 0,                        // A: x shared
        0, 128LL * 512,              // B: +s slab
        0, 128LL,                    // C: +s*128 col offset
        nullptr, 1.0f);
}